// round 17
// baseline (speedup 1.0000x reference)
#include <cuda_runtime.h>
#include <cuda_bf16.h>

#define NCTA 128
#define TPB  512
#define OB0H 0
#define OB0L 32768
#define OB1H 65536
#define OB1L 131072
#define OAH  196608
#define OAL  212992
#define OXT  229376
#define SMEMB 230400

__device__ unsigned short g_h0h[2][128][256];
__device__ unsigned short g_h0l[2][128][256];
__device__ unsigned short g_h1h[2][128][256];
__device__ unsigned short g_h1l[2][128][256];
__device__ unsigned g_grp[8];

__device__ __forceinline__ float sigm(float x){ return __fdividef(1.f,1.f+__expf(-x)); }
__device__ __forceinline__ float tanha(float x){ return __fdividef(2.f,1.f+__expf(-2.f*x))-1.f; }
__device__ __forceinline__ void st16cg(unsigned short *p, unsigned short v){
    asm volatile("st.global.cg.u16 [%0], %1;" :: "l"(p), "h"(v) : "memory");
}
__device__ __forceinline__ unsigned short ld16cg(const unsigned short *p){
    unsigned short v;
    asm volatile("ld.global.cg.u16 %0, [%1];" : "=h"(v) : "l"(p));
    return v;
}
__device__ __forceinline__ void stsplit(unsigned short *ph, unsigned short *pl, float v){
    __nv_bfloat16 hi = __float2bfloat16(v);
    __nv_bfloat16 lo = __float2bfloat16(v - __bfloat162float(hi));
    st16cg(ph, __bfloat16_as_ushort(hi));
    st16cg(pl, __bfloat16_as_ushort(lo));
}
__device__ __forceinline__ unsigned smem_u32(const void *p){
    unsigned r;
    asm("{ .reg .u64 t1; cvta.to.shared.u64 t1, %1; cvt.u32.u64 %0, t1; }" : "=r"(r) : "l"(p));
    return r;
}
__device__ __forceinline__ void ldsm4(unsigned *r, unsigned a){
    asm volatile("ldmatrix.sync.aligned.m8n8.x4.shared.b16 {%0,%1,%2,%3}, [%4];"
                 : "=r"(r[0]),"=r"(r[1]),"=r"(r[2]),"=r"(r[3]) : "r"(a));
}
__device__ __forceinline__ void mma(float *d, const unsigned *a, const unsigned *b){
    asm volatile("mma.sync.aligned.m16n8k16.row.col.f32.bf16.bf16.f32 "
                 "{%0,%1,%2,%3}, {%4,%5,%6,%7}, {%8,%9}, {%0,%1,%2,%3};"
                 : "+f"(d[0]),"+f"(d[1]),"+f"(d[2]),"+f"(d[3])
                 : "r"(a[0]),"r"(a[1]),"r"(a[2]),"r"(a[3]), "r"(b[0]),"r"(b[1]));
}
__device__ __forceinline__ void grp_arrive(int bg){
    asm volatile("red.release.gpu.global.add.u32 [%0], %1;" :: "l"(&g_grp[bg]), "r"(1u) : "memory");
}
__device__ __forceinline__ void grp_wait(int bg, unsigned tgt){
    unsigned v, ns = 32;
    for(;;){
        asm volatile("ld.acquire.gpu.global.u32 %0, [%1];" : "=r"(v) : "l"(&g_grp[bg]) : "memory");
        if (v >= tgt) break;
        __nanosleep(ns); if (ns < 256) ns <<= 1;
    }
}
__device__ __forceinline__ void groupbar(int bg, unsigned tgt){
    __syncthreads();
    if (threadIdx.x == 0){ grp_arrive(bg); grp_wait(bg, tgt); }
    __syncthreads();
}

extern __shared__ char smb[];

__global__ __launch_bounds__(TPB, 1)
void regime_kernel(const float *__restrict__ X,    const float *__restrict__ vix,
                   const float *__restrict__ Wih0, const float *__restrict__ Whh0,
                   const float *__restrict__ bih0, const float *__restrict__ bhh0,
                   const float *__restrict__ Wih1, const float *__restrict__ Whh1,
                   const float *__restrict__ bih1, const float *__restrict__ bhh1,
                   const float *__restrict__ lng,  const float *__restrict__ lnb,
                   const float *__restrict__ lw,   const float *__restrict__ lb,
                   const float *__restrict__ rbud, float *__restrict__ out)
{
    const int t    = threadIdx.x;
    const int bid  = blockIdx.x;
    const int hg   = bid & 15;
    const int bg   = bid >> 4;
    const int w    = t >> 5;
    const int wn   = w & 7;          // n-octet (B rows 8wn..8wn+7)
    const int lane = t & 31;
    float *xtf = (float *)(smb + OXT);

    // ---- one-time weight conversion into swizzled bf16 hi/lo smem tiles ----
    for (int idx = t; idx < 16384; idx += TPB) {
        int n = idx >> 8, kk = idx & 255;
        int R = (n & 3) * 256 + hg * 16 + (n >> 2);
        float v = __ldg(Whh0 + R * 256 + kk);
        __nv_bfloat16 hi = __float2bfloat16(v);
        __nv_bfloat16 lo = __float2bfloat16(v - __bfloat162float(hi));
        int off = ((n << 9) + (kk << 1)) ^ ((n & 7) << 4);
        *(__nv_bfloat16 *)(smb + OB0H + off) = hi;
        *(__nv_bfloat16 *)(smb + OB0L + off) = lo;
    }
    for (int idx = t; idx < 32768; idx += TPB) {
        int n = idx >> 9, kk = idx & 511;
        int R = (n & 3) * 256 + hg * 16 + (n >> 2);
        float v = (kk < 256) ? __ldg(Wih1 + R * 256 + kk) : __ldg(Whh1 + R * 256 + kk - 256);
        __nv_bfloat16 hi = __float2bfloat16(v);
        __nv_bfloat16 lo = __float2bfloat16(v - __bfloat162float(hi));
        int off = ((n << 10) + (kk << 1)) ^ ((n & 7) << 4);
        *(__nv_bfloat16 *)(smb + OB1H + off) = hi;
        *(__nv_bfloat16 *)(smb + OB1L + off) = lo;
    }

    // per-lane epilogue identities (used by warps 0-7)
    const int q   = lane & 3;
    const int n0  = 2 * q;
    const int R0  = (n0 & 3) * 256 + hg * 16 + (2 * wn + (n0 >> 2));
    const int R1  = ((n0 + 1) & 3) * 256 + hg * 16 + (2 * wn + ((n0 + 1) >> 2));
    const int r   = lane >> 2;
    const int jl  = 2 * wn + (q >> 1);
    const bool oddq = (q & 1) != 0;
    float wx0[16], wx1[16];
#pragma unroll
    for (int i = 0; i < 16; i++) { wx0[i] = __ldg(Wih0 + R0 * 16 + i); wx1[i] = __ldg(Wih0 + R1 * 16 + i); }
    const float bb00 = bih0[R0] + bhh0[R0], bb01 = bih0[R1] + bhh0[R1];
    const float bb10 = bih1[R0] + bhh1[R0], bb11 = bih1[R1] + bhh1[R1];
    float cs0[2] = {0, 0}, cs1[2] = {0, 0};

    // ldmatrix addressing
    const unsigned smu = smem_u32(smb);
    const int sub = lane >> 3;
    const int arr = (sub & 1) * 8 + (lane & 7);
    const int akh = (sub >> 1) * 8;
    const unsigned aswz = (unsigned)((arr & 7) << 4);
    const unsigned aBH = smu + OAH + (arr << 10), aBL = smu + OAL + (arr << 10);
    const int brw = lane & 7, btk = (lane >> 3) * 8;
    const unsigned bswz = (unsigned)(brw << 4);
    const unsigned b1BH = smu + OB1H + ((8 * wn + brw) << 10);
    const unsigned b1BL = smu + OB1L + ((8 * wn + brw) << 10);
    const unsigned b0BH = smu + OB0H + ((8 * wn + brw) << 9);
    const unsigned b0BL = smu + OB0L + ((8 * wn + brw) << 9);

    // staging identity: plane pl, 4 16B chunks per thread
    const int pl = t >> 7, i0 = t & 127;
    __syncthreads();

    for (int k = 0; k <= 1024; k++) {
        const int pp = (k - 1) & 1;
        // ---- stage hi/lo planes -> A tiles (pure 16B copies, swizzled) ----
#pragma unroll
        for (int cc = 0; cc < 4; cc++) {
            int c = i0 + (cc << 7);
            int b = c >> 5, kc = c & 31;
            uint4 v = make_uint4(0, 0, 0, 0);
            const unsigned short *src =
                (pl == 0) ? &g_h0h[pp][bg * 16 + b][kc * 8] :
                (pl == 1) ? &g_h0l[pp][bg * 16 + b][kc * 8] :
                (pl == 2) ? &g_h1h[pp][bg * 16 + b][kc * 8] :
                            &g_h1l[pp][bg * 16 + b][kc * 8];
            bool ld = (pl < 2) ? (k > 0) : (k > 1);
            if (ld) v = __ldcg((const uint4 *)src);
            int off = ((b << 10) + ((pl >= 2) ? 512 : 0) + (kc << 4)) ^ ((b & 7) << 4);
            *(uint4 *)(smb + ((pl & 1) ? OAL : OAH) + off) = v;
        }
        if (k < 1024 && t < 64) {
            int bl = t >> 2, i4 = t & 3;
            ((float4 *)xtf)[t] = __ldg((const float4 *)(X + ((bg * 16 + bl) * 1024 + k) * 16 + i4 * 4));
        }
        __syncthreads();

        // ---- MMA, K-split: warps 0-7 = d0 full + d1 k<128; warps 8-15 = d1 k>=128 ----
        float d0[4] = {0,0,0,0}, d1[4] = {0,0,0,0};
        if (t < 256) {
#pragma unroll 2
            for (int c = 0; c < 8; c++) {
                const int kw = c << 5;
                unsigned A0h[4],A1h[4],A0l[4],A1l[4],B0h[4],B0l[4];
                ldsm4(A0h, (aBH + ((kw + akh) << 1)) ^ aswz);
                ldsm4(A1h, (aBH + ((kw + 16 + akh) << 1)) ^ aswz);
                ldsm4(A0l, (aBL + ((kw + akh) << 1)) ^ aswz);
                ldsm4(A1l, (aBL + ((kw + 16 + akh) << 1)) ^ aswz);
                ldsm4(B0h, (b0BH + ((kw + btk) << 1)) ^ bswz);
                ldsm4(B0l, (b0BL + ((kw + btk) << 1)) ^ bswz);
                mma(d0, A0h, &B0h[0]); mma(d0, A0h, &B0l[0]); mma(d0, A0l, &B0h[0]);
                mma(d0, A1h, &B0h[2]); mma(d0, A1h, &B0l[2]); mma(d0, A1l, &B0h[2]);
                if (c < 4) {
                    unsigned B1h[4],B1l[4];
                    ldsm4(B1h, (b1BH + ((kw + btk) << 1)) ^ bswz);
                    ldsm4(B1l, (b1BL + ((kw + btk) << 1)) ^ bswz);
                    mma(d1, A0h, &B1h[0]); mma(d1, A0h, &B1l[0]); mma(d1, A0l, &B1h[0]);
                    mma(d1, A1h, &B1h[2]); mma(d1, A1h, &B1l[2]); mma(d1, A1l, &B1h[2]);
                }
            }
        } else {
#pragma unroll 2
            for (int c = 0; c < 12; c++) {
                const int kw = 128 + (c << 5);
                unsigned A0h[4],A1h[4],A0l[4],A1l[4],B1h[4],B1l[4];
                ldsm4(A0h, (aBH + ((kw + akh) << 1)) ^ aswz);
                ldsm4(A1h, (aBH + ((kw + 16 + akh) << 1)) ^ aswz);
                ldsm4(A0l, (aBL + ((kw + akh) << 1)) ^ aswz);
                ldsm4(A1l, (aBL + ((kw + 16 + akh) << 1)) ^ aswz);
                ldsm4(B1h, (b1BH + ((kw + btk) << 1)) ^ bswz);
                ldsm4(B1l, (b1BL + ((kw + btk) << 1)) ^ bswz);
                mma(d1, A0h, &B1h[0]); mma(d1, A0h, &B1l[0]); mma(d1, A0l, &B1h[0]);
                mma(d1, A1h, &B1h[2]); mma(d1, A1h, &B1l[2]); mma(d1, A1l, &B1h[2]);
            }
        }

        // ---- reduce d1 across K-halves through (dead) A-hi region ----
        __syncthreads();
        if (t >= 256)
            ((float4 *)(smb + OAH))[t - 256] = make_float4(d1[0], d1[1], d1[2], d1[3]);
        __syncthreads();

        if (t < 256) {
            float4 v = ((float4 *)(smb + OAH))[t];
            d1[0] += v.x; d1[1] += v.y; d1[2] += v.z; d1[3] += v.w;

            if (k < 1024) {
                const float *xr0 = xtf + r * 16, *xr8 = xtf + (r + 8) * 16;
                float x00=0, x01=0, x80=0, x81=0;
#pragma unroll
                for (int i = 0; i < 16; i++) {
                    float a = xr0[i], b8 = xr8[i];
                    x00 += wx0[i]*a; x01 += wx1[i]*a; x80 += wx0[i]*b8; x81 += wx1[i]*b8;
                }
                float e0 = d0[0]+bb00+x00, e1 = d0[1]+bb01+x01;
                float e2 = d0[2]+bb00+x80, e3 = d0[3]+bb01+x81;
                float a0 = oddq ? tanha(e0) : sigm(e0);
                float a1 = sigm(e1);
                float a2 = oddq ? tanha(e2) : sigm(e2);
                float a3 = sigm(e3);
                float p0 = __shfl_xor_sync(0xffffffffu, a0, 1);
                float p1 = __shfl_xor_sync(0xffffffffu, a1, 1);
                float p2 = __shfl_xor_sync(0xffffffffu, a2, 1);
                float p3 = __shfl_xor_sync(0xffffffffu, a3, 1);
                if (!oddq) {
                    cs0[0] = a1 * cs0[0] + a0 * p0;
                    cs0[1] = a3 * cs0[1] + a2 * p2;
                    stsplit(&g_h0h[k & 1][bg*16 + r][hg*16 + jl],
                            &g_h0l[k & 1][bg*16 + r][hg*16 + jl], p1 * tanha(cs0[0]));
                    stsplit(&g_h0h[k & 1][bg*16 + r + 8][hg*16 + jl],
                            &g_h0l[k & 1][bg*16 + r + 8][hg*16 + jl], p3 * tanha(cs0[1]));
                }
            }
            if (k >= 1) {
                float e0 = d1[0]+bb10, e1 = d1[1]+bb11, e2 = d1[2]+bb10, e3 = d1[3]+bb11;
                float a0 = oddq ? tanha(e0) : sigm(e0);
                float a1 = sigm(e1);
                float a2 = oddq ? tanha(e2) : sigm(e2);
                float a3 = sigm(e3);
                float p0 = __shfl_xor_sync(0xffffffffu, a0, 1);
                float p1 = __shfl_xor_sync(0xffffffffu, a1, 1);
                float p2 = __shfl_xor_sync(0xffffffffu, a2, 1);
                float p3 = __shfl_xor_sync(0xffffffffu, a3, 1);
                if (!oddq) {
                    cs1[0] = a1 * cs1[0] + a0 * p0;
                    cs1[1] = a3 * cs1[1] + a2 * p2;
                    stsplit(&g_h1h[k & 1][bg*16 + r][hg*16 + jl],
                            &g_h1l[k & 1][bg*16 + r][hg*16 + jl], p1 * tanha(cs1[0]));
                    stsplit(&g_h1h[k & 1][bg*16 + r + 8][hg*16 + jl],
                            &g_h1l[k & 1][bg*16 + r + 8][hg*16 + jl], p3 * tanha(cs1[1]));
                }
            }
        }
        groupbar(bg, 16u * (unsigned)(k + 1));
    }

    if (t == 0) grp_arrive(bg);   // done-pass for reset

    // ---- head on hg==0 CTA (h1 final at parity 0, visible after last groupbar) ----
    if (hg == 0) {
        if (t < 16) {
            const int b = bg * 16 + t;
            float hv[256];
            float s = 0.f, s2 = 0.f;
            for (int i = 0; i < 256; i++) {
                float v = __bfloat162float(__ushort_as_bfloat16(ld16cg(&g_h1h[0][b][i]))) +
                          __bfloat162float(__ushort_as_bfloat16(ld16cg(&g_h1l[0][b][i])));
                hv[i] = v; s += v; s2 += v * v;
            }
            float mu  = s * (1.f/256.f);
            float var = s2 * (1.f/256.f) - mu * mu;
            float inv = rsqrtf(var + 1e-5f);
            float l0 = lb[0], l1 = lb[1], l2 = lb[2];
            for (int i = 0; i < 256; i++) {
                float hn = (hv[i] - mu) * inv * lng[i] + lnb[i];
                l0 += hn * lw[i]; l1 += hn * lw[256 + i]; l2 += hn * lw[512 + i];
            }
            float m  = fmaxf(l0, fmaxf(l1, l2));
            float e0 = __expf(l0-m), e1 = __expf(l1-m), e2 = __expf(l2-m);
            float es = e0 + e1 + e2;
            float p0 = e0/es, p1 = e1/es, p2 = e2/es;
            float bm[3], bs[3];
#pragma unroll
            for (int rr = 0; rr < 3; rr++) {
                float mm = -1e30f;
                for (int p = 0; p < 32; p++) mm = fmaxf(mm, rbud[rr*32+p]);
                float sx = 0.f;
                for (int p = 0; p < 32; p++) sx += __expf(rbud[rr*32+p] - mm);
                bm[rr] = mm; bs[rr] = sx;
            }
            float w0s = p0/bs[0], w1s = p1/bs[1], w2s = p2/bs[2];
            float bbv[32], eqs = 0.f, dfs = 0.f;
            for (int p = 0; p < 32; p++) {
                float v = w0s*__expf(rbud[p]-bm[0]) + w1s*__expf(rbud[32+p]-bm[1]) + w2s*__expf(rbud[64+p]-bm[2]);
                bbv[p] = v;
                if (p < 24) eqs += v; else dfs += v;
            }
            bool  mask = vix[b] >= 30.0f;
            float shortfall = 0.4f - dfs;
            float ratio = fminf(shortfall / fmaxf(eqs, 1e-8f), 0.8f);
            bool  apply = mask && (shortfall > 0.f) && (eqs > 1e-8f);
            float bsum = 0.f, bsel[32];
            for (int p = 0; p < 32; p++) {
                float b2 = (p < 24) ? bbv[p]*(1.f-ratio) : bbv[p] + shortfall*(1.f/8.f);
                float v  = apply ? b2 : bbv[p];
                bsel[p] = v; bsum += v;
            }
            float innorm = 1.f / (bsum + 1e-8f);
            for (int p = 0; p < 32; p++)
                out[b*32+p] = mask ? bsel[p]*innorm : bbv[p];
            out[4096 + b*3 + 0] = p0;
            out[4096 + b*3 + 1] = p1;
            out[4096 + b*3 + 2] = p2;
        }
        if (t == 0) {
            grp_wait(bg, 16u * 1026u);
            asm volatile("st.relaxed.gpu.global.u32 [%0], %1;" :: "l"(&g_grp[bg]), "r"(0u) : "memory");
        }
    }
}

extern "C" void kernel_launch(void *const *d_in, const int *in_sizes, int n_in,
                              void *d_out, int out_size)
{
    (void)in_sizes; (void)n_in; (void)out_size;
    static int inited = 0;
    if (!inited) {
        cudaFuncSetAttribute(regime_kernel, cudaFuncAttributeMaxDynamicSharedMemorySize, SMEMB);
        inited = 1;
    }
    regime_kernel<<<NCTA, TPB, SMEMB>>>(
        (const float *)d_in[0],  (const float *)d_in[1],  (const float *)d_in[2],
        (const float *)d_in[3],  (const float *)d_in[4],  (const float *)d_in[5],
        (const float *)d_in[6],  (const float *)d_in[7],  (const float *)d_in[8],
        (const float *)d_in[9],  (const float *)d_in[10], (const float *)d_in[11],
        (const float *)d_in[12], (const float *)d_in[13], (const float *)d_in[14],
        (float *)d_out);
}